// round 8
// baseline (speedup 1.0000x reference)
#include <cuda_runtime.h>
#include <cuda_bf16.h>
#include <cstdint>

// ---------------------------------------------------------------------------
// RNN_MultiRegional_SAC — bf16 mma.sync, 4-way K-split, all-tiles-prefetched.
// h = relu(0.9 h + 0.1 (h @ W^T + drive)), 512 steps, B=32, 3H=3072.
// W_rec: 5 nonzero 1024x1024 blocks bf16: [W00=-fixed, W02, W10, W21, W22]
//   n 0..1023:    W00 (k: h[0:1024])    + W02 (k: h[2048:3072])
//   n 1024..2047: W10 (k: h[0:1024])
//   n 2048..3071: W21 (k: h[1024:2048]) + W22 (k: h[2048:3072])
// Grid 320 blocks/step, each exactly 4 K128-tiles (512 K) over a 32-n strip:
//   bid 0..127:   str strips (4 parts: W00-lo, W00-hi, W02-lo, W02-hi)
//   bid 128..255: m1 strips  (4 parts: W21-lo, W21-hi, W22-lo, W22-hi)
//   bid 256..319: thal strips (2 parts: W10-lo, W10-hi)
// All parts write fp32 partials; per-(t,group) atomic counter; LAST arriver
// re-reads all partials in fixed order (bit-deterministic) + epilogue.
// Output (float32): [mean 32*512][std 32*512][hn_last 32*3072][rnn 32*512*3072]
// ---------------------------------------------------------------------------

#define Hh   1024
#define H3   3072
#define Bz   32
#define Tz   512
#define NEXC 717
#define HH   (Hh*Hh)
#define NGRP 96

__device__ __align__(256) __nv_bfloat16 g_Wb[5u * HH];      // 10 MB
__device__ __align__(256) float         g_hf[2][Bz * H3];   // fp32 master h [b][n]
__device__ __align__(256) __nv_bfloat16 g_hb[2][Bz * H3];   // bf16 operand h [b][n]
__device__ __align__(256) float         g_part[NGRP * 4 * 1024]; // [group][part][n32*b32]
__device__ int g_flag[Tz * NGRP];                            // per-(step,group) arrivals

// ---------------- helpers ----------------
__device__ __forceinline__ void cp16(unsigned dst, const void* src) {
    asm volatile("cp.async.cg.shared.global [%0], [%1], 16;" :: "r"(dst), "l"(src));
}
#define CP_COMMIT() asm volatile("cp.async.commit_group;")

__device__ __forceinline__ unsigned smem_u32(const void* p) {
    return (unsigned)__cvta_generic_to_shared(p);
}

// ---------------- prep: build packed bf16 W blocks + zero flags ----------------
__global__ void prep_kernel(const float* __restrict__ w_str2thal,
                            const float* __restrict__ w_m12m1,
                            const float* __restrict__ w_m12str,
                            const float* __restrict__ w_thal2m1,
                            const float* __restrict__ fixedw) {
    int idx = blockIdx.x * blockDim.x + threadIdx.x;
    if (idx >= HH) return;
    if (idx < Tz * NGRP) g_flag[idx] = 0;
    int c = idx & (Hh - 1);
    g_Wb[0u * HH + idx] = __float2bfloat16(-fixedw[idx]);
    float v = fminf(fmaxf(w_m12str[idx], 1e-10f), 1.0f);
    g_Wb[1u * HH + idx] = __float2bfloat16((c < NEXC) ? v : 0.0f);
    v = fminf(fmaxf(w_str2thal[idx], 1e-10f), 1.0f);
    g_Wb[2u * HH + idx] = __float2bfloat16((c < (Hh / 2)) ? v : -v);
    g_Wb[3u * HH + idx] = __float2bfloat16(fminf(fmaxf(w_thal2m1[idx], 1e-10f), 1.0f));
    v = fminf(fmaxf(w_m12m1[idx], 1e-10f), 1.0f);
    g_Wb[4u * HH + idx] = __float2bfloat16((c < NEXC) ? v : -v);
}

// ---------------- init: hn ([1][32][3072] = [b][n]) -> h masters ---------------
__global__ void init_kernel(const float* __restrict__ hn) {
    int idx = blockIdx.x * blockDim.x + threadIdx.x;
    if (idx >= Bz * H3) return;
    float v = hn[idx];
    g_hf[0][idx] = v;
    g_hb[0][idx] = __float2bfloat16(v);
}

// ---------------- per-step tensor-core kernel ----------------------------------
// 256 threads = 8 warps; warp = (bt = w&1: batch half, nh = w>>1: n-octet).
// Each warp: 512-K (4 tiles) for a 16b x 8n fragment. All 4 tiles prefetched
// into 4 smem buffers before compute; wait_group 3/2/1/0 per tile.
// Dynamic smem 64KB: sW[4][8192] then sH[4][8192]; XOR swizzle chunk16^=row&7.
__global__ void __launch_bounds__(256) step_mma(int t,
                                                const float* __restrict__ inp,
                                                const float* __restrict__ iw,
                                                float* __restrict__ rnn) {
    extern __shared__ __align__(256) unsigned char smem[];
    __shared__ int swin;

    const int tx   = threadIdx.x;
    const int bid  = blockIdx.x;
    const int wid  = tx >> 5;
    const int lane = tx & 31;
    const int cur  = t & 1, nxt = cur ^ 1;

    // ---- block decode ----
    int n0, group, part, nparts, hoff, wkoff;
    const __nv_bfloat16* wsrc;
    if (bid < 128) {
        int strip = bid >> 2; part = bid & 3; group = strip; nparts = 4;
        int kh = part >> 1, kq = part & 1;
        n0 = strip * 32;
        wsrc = kh ? g_Wb + 1u * HH : g_Wb;
        wkoff = kq * 512;
        hoff  = (kh ? 2048 : 0) + kq * 512;
    } else if (bid < 256) {
        int idx2 = bid - 128;
        int strip = idx2 >> 2; part = idx2 & 3; group = 32 + strip; nparts = 4;
        int kh = part >> 1, kq = part & 1;
        n0 = 2048 + strip * 32;
        wsrc = kh ? g_Wb + 4u * HH : g_Wb + 3u * HH;
        wkoff = kq * 512;
        hoff  = (kh ? 2048 : 1024) + kq * 512;
    } else {
        int idx2 = bid - 256;
        int strip = idx2 >> 1; part = idx2 & 1; group = 64 + strip; nparts = 2;
        n0 = 1024 + strip * 32;
        wsrc = g_Wb + 2u * HH;
        wkoff = part * 512;
        hoff  = part * 512;
    }
    const int nloc = n0 & (Hh - 1);

    const __nv_bfloat16* __restrict__ hbcur = g_hb[cur];
    const unsigned sWaddr = smem_u32(smem);            // 4 x 8192
    const unsigned sHaddr = sWaddr + 32768;            // 4 x 8192

    // ---- stage all 4 tiles upfront (one commit group per tile) ----
    const __nv_bfloat16* wrow = wsrc + (size_t)nloc * Hh + wkoff;
    const __nv_bfloat16* hrow = hbcur + hoff;
    {
        const int r = tx >> 4, col0 = tx & 15;          // thread's 2 chunks: col0, col0 (second half rows)
#pragma unroll
        for (int kt = 0; kt < 4; kt++) {
#pragma unroll
            for (int i = 0; i < 2; i++) {
                int c = tx + i * 256;
                int rr = c >> 4, col = c & 15;
                unsigned off = rr * 256 + ((col ^ (rr & 7)) << 4);
                cp16(sWaddr + kt * 8192 + off, wrow + (size_t)rr * Hh + (kt << 7) + col * 8);
                cp16(sHaddr + kt * 8192 + off, hrow + (size_t)rr * H3 + (kt << 7) + col * 8);
            }
            CP_COMMIT();
        }
        (void)r; (void)col0;
    }

    // ---- ldmatrix lane addressing ----
    const int bt = wid & 1, nh = wid >> 1;
    const int am = lane >> 3;
    const int arow = bt * 16 + (am & 1) * 8 + (lane & 7);   // A row (batch)
    const int qa   = am >> 1;
    const int sa   = arow & 7;
    const int brow = nh * 8 + (lane & 7);                   // B row (n)
    const int grp  = lane >> 3;
    const int sb   = brow & 7;
    const unsigned habase = sHaddr + arow * 256;
    const unsigned wbbase = sWaddr + brow * 256;

    float d[2][4];
#pragma unroll
    for (int e = 0; e < 2; e++)
#pragma unroll
        for (int j = 0; j < 4; j++) d[e][j] = 0.f;

    // ---- compute 4 tiles, waiting progressively ----
#pragma unroll
    for (int kt = 0; kt < 4; kt++) {
        if (kt == 0) asm volatile("cp.async.wait_group 3;");
        else if (kt == 1) asm volatile("cp.async.wait_group 2;");
        else if (kt == 2) asm volatile("cp.async.wait_group 1;");
        else asm volatile("cp.async.wait_group 0;");
        __syncthreads();

        const unsigned ha = habase + kt * 8192;
        const unsigned wa = wbbase + kt * 8192;
#pragma unroll
        for (int kp = 0; kp < 4; kp++) {
            unsigned b0, b1, b2, b3;
            asm volatile("ldmatrix.sync.aligned.m8n8.x4.shared.b16 {%0,%1,%2,%3}, [%4];"
                         : "=r"(b0), "=r"(b1), "=r"(b2), "=r"(b3)
                         : "r"(wa + (((4 * kp + grp) ^ sb) << 4)));
            unsigned a0, a1, a2, a3;
            asm volatile("ldmatrix.sync.aligned.m8n8.x4.shared.b16 {%0,%1,%2,%3}, [%4];"
                         : "=r"(a0), "=r"(a1), "=r"(a2), "=r"(a3)
                         : "r"(ha + (((4 * kp + qa) ^ sa) << 4)));
            asm volatile("mma.sync.aligned.m16n8k16.row.col.f32.bf16.bf16.f32 "
                         "{%0,%1,%2,%3}, {%4,%5,%6,%7}, {%8,%9}, {%0,%1,%2,%3};"
                         : "+f"(d[0][0]), "+f"(d[0][1]), "+f"(d[0][2]), "+f"(d[0][3])
                         : "r"(a0), "r"(a1), "r"(a2), "r"(a3), "r"(b0), "r"(b1));
            unsigned c0, c1, c2, c3;
            asm volatile("ldmatrix.sync.aligned.m8n8.x4.shared.b16 {%0,%1,%2,%3}, [%4];"
                         : "=r"(c0), "=r"(c1), "=r"(c2), "=r"(c3)
                         : "r"(ha + (((4 * kp + 2 + qa) ^ sa) << 4)));
            asm volatile("mma.sync.aligned.m16n8k16.row.col.f32.bf16.bf16.f32 "
                         "{%0,%1,%2,%3}, {%4,%5,%6,%7}, {%8,%9}, {%0,%1,%2,%3};"
                         : "+f"(d[1][0]), "+f"(d[1][1]), "+f"(d[1][2]), "+f"(d[1][3])
                         : "r"(c0), "r"(c1), "r"(c2), "r"(c3), "r"(b2), "r"(b3));
        }
    }

    float ds[4];
#pragma unroll
    for (int j = 0; j < 4; j++) ds[j] = d[0][j] + d[1][j];

    // fragment coords: ds[half*2+j] -> (b = pb + half*8, n = n0 + pn + j)
    const int g  = lane >> 2, tg = lane & 3;
    const int pn = nh * 8 + 2 * tg;
    const int pb = bt * 16 + g;

    // ---- write partial; last arriver combines (canonical order) + epilogue ----
    {
        float* pp = g_part + (group * 4 + part) * 1024;
#pragma unroll
        for (int half = 0; half < 2; half++)
#pragma unroll
            for (int j = 0; j < 2; j++)
                pp[(pn + j) * 32 + pb + half * 8] = ds[half * 2 + j];
        __threadfence();
        __syncthreads();
        if (tx == 0) swin = atomicAdd(&g_flag[t * NGRP + group], 1);
        __syncthreads();
        if (swin != nparts - 1) return;      // not last: partner(s) will finish
        __threadfence();                     // acquire

        float s[4] = {0.f, 0.f, 0.f, 0.f};
#pragma unroll 1
        for (int p = 0; p < nparts; p++) {
            const float* qq = g_part + (group * 4 + p) * 1024;
#pragma unroll
            for (int half = 0; half < 2; half++)
#pragma unroll
                for (int j = 0; j < 2; j++)
                    s[half * 2 + j] += __ldcg(&qq[(pn + j) * 32 + pb + half * 8]);
        }
#pragma unroll
        for (int j = 0; j < 4; j++) ds[j] = s[j];
    }

    // ---- epilogue: drive + relu update; write h masters + rnn ----
    {
        const int ncol = n0 + pn;
        float* __restrict__ hfn = g_hf[nxt];
        __nv_bfloat16* __restrict__ hbn = g_hb[nxt];
        const float* __restrict__ hfc = g_hf[cur];

        float iwv[2][4];
#pragma unroll
        for (int j = 0; j < 2; j++)
#pragma unroll
            for (int i = 0; i < 4; i++) iwv[j][i] = iw[i * H3 + ncol + j];

#pragma unroll
        for (int half = 0; half < 2; half++) {
            int b = pb + half * 8;
            float4 iv = ((const float4*)inp)[b * Tz + t];
#pragma unroll
            for (int j = 0; j < 2; j++) {
                int n = ncol + j;
                float drv = iv.x * iwv[j][0] + iv.y * iwv[j][1]
                          + iv.z * iwv[j][2] + iv.w * iwv[j][3];
                float hp = hfc[b * H3 + n];
                float v = fmaxf(0.9f * hp + 0.1f * (ds[half * 2 + j] + drv), 0.0f);
                hfn[b * H3 + n] = v;
                hbn[b * H3 + n] = __float2bfloat16(v);
                rnn[((size_t)(b * Tz + t)) * H3 + n] = v;
            }
        }
    }
}

// ---------------- heads: mean/std over masked (m1) region ----------------------
__global__ void head_kernel(const float* __restrict__ rnn,
                            const float* __restrict__ mean_w, const float* __restrict__ mean_b,
                            const float* __restrict__ std_w,  const float* __restrict__ std_b,
                            float* __restrict__ mean_out, float* __restrict__ std_out) {
    int warp = blockIdx.x * 8 + (threadIdx.x >> 5);   // = b*512 + t
    int lane = threadIdx.x & 31;
    const float* row = rnn + (size_t)warp * H3 + 2048;
    float sm = 0.0f, ss = 0.0f;
#pragma unroll 8
    for (int i = lane; i < Hh; i += 32) {
        float v = row[i];
        sm += v * mean_w[2048 + i];
        ss += v * std_w[2048 + i];
    }
#pragma unroll
    for (int off = 16; off; off >>= 1) {
        sm += __shfl_down_sync(0xFFFFFFFFu, sm, off);
        ss += __shfl_down_sync(0xFFFFFFFFu, ss, off);
    }
    if (lane == 0) {
        mean_out[warp] = sm + mean_b[0];
        float s = ss + std_b[0];
        std_out[warp] = fminf(fmaxf(s, -5.0f), 10.0f);
    }
}

// ---------------- hn_last copy --------------------------------------------------
__global__ void hn_kernel(const float* __restrict__ rnn, float* __restrict__ hn_out) {
    int idx = blockIdx.x * blockDim.x + threadIdx.x;
    if (idx >= Bz * H3) return;
    int b = idx / H3, n = idx - b * H3;
    hn_out[idx] = rnn[((size_t)(b * Tz + (Tz - 1))) * H3 + n];
}

// ---------------- launch ---------------------------------------------------------
extern "C" void kernel_launch(void* const* d_in, const int* in_sizes, int n_in,
                              void* d_out, int out_size) {
    const float* inp        = (const float*)d_in[0];   // [32,512,4]
    const float* hn         = (const float*)d_in[1];   // [1,32,3072]
    // d_in[2] = w_str2str (unused: its mask is all-zeros in the reference)
    const float* w_str2thal = (const float*)d_in[3];
    const float* w_m12m1    = (const float*)d_in[4];
    const float* w_m12str   = (const float*)d_in[5];
    const float* w_thal2m1  = (const float*)d_in[6];
    const float* fixedw     = (const float*)d_in[7];
    const float* inp_weight = (const float*)d_in[8];   // [4,3072]
    const float* mean_w     = (const float*)d_in[9];   // [1,3072]
    const float* mean_b     = (const float*)d_in[10];  // [1]
    const float* std_w      = (const float*)d_in[11];
    const float* std_b      = (const float*)d_in[12];
    // d_in[13] = sampling flag

    float* out      = (float*)d_out;
    float* mean_out = out;                         // 32*512
    float* std_out  = out + 16384;                 // 32*512
    float* hn_out   = out + 32768;                 // 32*3072
    float* rnn      = out + 131072;                // 32*512*3072

    static int smem_set = 0;
    if (!smem_set) {
        cudaFuncSetAttribute(step_mma, cudaFuncAttributeMaxDynamicSharedMemorySize, 65536);
        smem_set = 1;
    }

    prep_kernel<<<(HH + 255) / 256, 256>>>(w_str2thal, w_m12m1, w_m12str, w_thal2m1, fixedw);
    init_kernel<<<(Bz * H3 + 255) / 256, 256>>>(hn);

    for (int t = 0; t < Tz; t++)
        step_mma<<<320, 256, 65536>>>(t, inp, inp_weight, rnn);

    head_kernel<<<2048, 256>>>(rnn, mean_w, mean_b, std_w, std_b, mean_out, std_out);
    hn_kernel<<<(Bz * H3 + 255) / 256, 256>>>(rnn, hn_out);
}

// round 9
// speedup vs baseline: 1.1621x; 1.1621x over previous
#include <cuda_runtime.h>
#include <cuda_bf16.h>
#include <cstdint>

// ---------------------------------------------------------------------------
// RNN_MultiRegional_SAC — bf16 mma.sync + cp.async.bulk (TMA-path) staging.
// h = relu(0.9 h + 0.1 (h @ W^T + drive)), 512 steps, B=32, 3H=3072.
// Key change vs R7: W and h operand tiles live in gmem as CONTIGUOUS,
// PRE-SWIZZLED 8KB tiles; staging uses cp.async.bulk + mbarrier (UBLKCP,
// LTS-capped, no per-16B L1tex wavefront cost that capped R5-R8 at ~9us/step).
// Grid 160 blocks/step, each 8 K128-tiles over a 32-n strip (R7 partition):
//   bid 0..63:   str  pair=bid>>1, khalf=bid&1 (W00 | W02)
//   bid 64..127: m1   pair=32+((bid-64)>>1)    (W21 | W22)
//   bid 128..159: thal (W10), no pairing
// Paired halves combine via gmem partials + per-(t,pair) atomic flag
// (second arriver finishes). fp32 master h; bf16 mma operands.
// Output (float32): [mean 32*512][std 32*512][hn_last 32*3072][rnn 32*512*3072]
// ---------------------------------------------------------------------------

#define Hh   1024
#define H3   3072
#define Bz   32
#define Tz   512
#define NEXC 717
#define HH   (Hh*Hh)

// Packed, per-block-contiguous, pre-swizzled W tiles: [bid 160][kt 8][4096 bf16]
__device__ __align__(256) __nv_bfloat16 g_Wp[160u * 8u * 4096u];   // 10 MB
__device__ __align__(256) float         g_hf[2][Bz * H3];          // fp32 master h [b][n]
// bf16 operand h, tiled+swizzled: 24 tiles of 4096 elems; tile tk holds k in
// [tk*128,(tk+1)*128): elem off = b*128 + ((((k>>3)&15)^(b&7))<<3) + (k&7)
__device__ __align__(256) __nv_bfloat16 g_hb[2][24 * 4096];
__device__ __align__(256) float         g_part[64 * 2 * 1024];     // [pair][khalf][n32*b32]
__device__ int g_flag[Tz * 64];                                     // per-(step,pair) arrivals

// ---------------- helpers ----------------
__device__ __forceinline__ unsigned smem_u32(const void* p) {
    return (unsigned)__cvta_generic_to_shared(p);
}
__device__ __forceinline__ void bulk_cp(unsigned dstS, const void* srcG, unsigned mbarS) {
    asm volatile("cp.async.bulk.shared::cta.global.mbarrier::complete_tx::bytes [%0], [%1], %2, [%3];"
                 :: "r"(dstS), "l"(srcG), "n"(8192), "r"(mbarS) : "memory");
}
__device__ __forceinline__ void mbar_init(unsigned mbarS) {
    asm volatile("mbarrier.init.shared.b64 [%0], 1;" :: "r"(mbarS) : "memory");
}
__device__ __forceinline__ void mbar_expect(unsigned mbarS, unsigned bytes) {
    asm volatile("mbarrier.arrive.expect_tx.shared.b64 _, [%0], %1;" :: "r"(mbarS), "r"(bytes) : "memory");
}
__device__ __forceinline__ void mbar_wait0(unsigned mbarS) {
    asm volatile(
        "{\n\t.reg .pred P;\n"
        "W_%=:\n\t"
        "mbarrier.try_wait.parity.acquire.cta.shared::cta.b64 P, [%0], 0, 0x989680;\n\t"
        "@P bra D_%=;\n\t"
        "bra W_%=;\n"
        "D_%=:\n\t}"
        :: "r"(mbarS) : "memory");
}

// ---------------- prep: pack W into per-block swizzled tiles + zero flags ------
// Destination-driven: one thread per packed bf16 element (160*8*4096 = 5.24M).
__global__ void prep_pack(const float* __restrict__ w_str2thal,
                          const float* __restrict__ w_m12m1,
                          const float* __restrict__ w_m12str,
                          const float* __restrict__ w_thal2m1,
                          const float* __restrict__ fixedw) {
    int e = blockIdx.x * blockDim.x + threadIdx.x;
    if (e >= 160 * 8 * 4096) return;
    if (e < Tz * 64) g_flag[e] = 0;

    int bid = e >> 15;              // /32768
    int rem = e & 32767;
    int kt  = rem >> 12;
    int wi  = rem & 4095;
    int row = wi >> 7;              // n within 32-strip
    int chunkS = (wi >> 3) & 15;
    int chunk  = chunkS ^ (row & 7);
    int kl  = (chunk << 3) | (wi & 7);    // k within 128-tile

    int n0loc, region;
    if (bid < 64)       { int strip = bid >> 1;        n0loc = strip * 32; region = (bid & 1) ? 1 : 0; }
    else if (bid < 128) { int strip = (bid - 64) >> 1; n0loc = strip * 32; region = (bid & 1) ? 4 : 3; }
    else                { n0loc = (bid - 128) * 32;    region = 2; }

    int n = n0loc + row;
    int k = (kt << 7) + kl;
    int src = n * Hh + k;

    float val;
    if (region == 0)      val = -fixedw[src];
    else if (region == 1) { float v = fminf(fmaxf(w_m12str[src], 1e-10f), 1.0f);  val = (k < NEXC) ? v : 0.0f; }
    else if (region == 2) { float v = fminf(fmaxf(w_str2thal[src], 1e-10f), 1.0f); val = (k < (Hh/2)) ? v : -v; }
    else if (region == 3) val = fminf(fmaxf(w_thal2m1[src], 1e-10f), 1.0f);
    else                  { float v = fminf(fmaxf(w_m12m1[src], 1e-10f), 1.0f);   val = (k < NEXC) ? v : -v; }

    g_Wp[e] = __float2bfloat16(val);
}

// ---------------- init: hn ([b][n]) -> h masters --------------------------------
__global__ void init_kernel(const float* __restrict__ hn) {
    int idx = blockIdx.x * blockDim.x + threadIdx.x;
    if (idx >= Bz * H3) return;
    int b = idx / H3, n = idx - b * H3;
    float v = hn[idx];
    g_hf[0][idx] = v;
    int off = (n >> 7) * 4096 + b * 128 + ((((n >> 3) & 15) ^ (b & 7)) << 3) + (n & 7);
    g_hb[0][off] = __float2bfloat16(v);
}

// ---------------- per-step tensor-core kernel ------------------------------------
// 256 threads = 8 warps; warp = (bt = w&1: batch half, nh = w>>1: n-octet).
// Each warp: 1024-K (8 tiles) for a 16b x 8n fragment. 4-buffer smem ring,
// 8 single-use mbarriers, cp.async.bulk staging (W-tile + h-tile per barrier).
__global__ void __launch_bounds__(256, 2) step_mma(int t,
                                                   const float* __restrict__ inp,
                                                   const float* __restrict__ iw,
                                                   float* __restrict__ rnn) {
    extern __shared__ __align__(256) unsigned char smem[];   // 4 x (8KB W + 8KB H)
    __shared__ __align__(8) unsigned long long mbar[8];
    __shared__ int swin;

    const int tx   = threadIdx.x;
    const int bid  = blockIdx.x;
    const int wid  = tx >> 5;
    const int lane = tx & 31;
    const int cur  = t & 1, nxt = cur ^ 1;

    // ---- block decode (R7 partition) ----
    int n0, pair, khalf, htile0;
    bool thal = false;
    if (bid < 64)       { int s = bid >> 1;        khalf = bid & 1; n0 = s * 32;        pair = s;      htile0 = khalf ? 16 : 0; }
    else if (bid < 128) { int s = (bid - 64) >> 1; khalf = bid & 1; n0 = 2048 + s * 32; pair = 32 + s; htile0 = khalf ? 16 : 8; }
    else                { int s = bid - 128;       khalf = 0;       n0 = 1024 + s * 32; pair = 0;      htile0 = 0; thal = true; }

    const __nv_bfloat16* __restrict__ wsrc = g_Wp + (size_t)bid * 32768;
    const __nv_bfloat16* __restrict__ hsrc = g_hb[cur] + htile0 * 4096;

    const unsigned sBase = smem_u32(smem);
    const unsigned mBase = smem_u32(mbar);

    // ---- init barriers, stage first 4 tiles ----
    if (tx == 0) {
#pragma unroll
        for (int i = 0; i < 8; i++) mbar_init(mBase + i * 8);
    }
    __syncthreads();
    if (tx == 0) {
#pragma unroll
        for (int i = 0; i < 4; i++) {
            unsigned mb = mBase + i * 8;
            mbar_expect(mb, 16384);
            bulk_cp(sBase + (i & 3) * 16384,        wsrc + i * 4096, mb);
            bulk_cp(sBase + (i & 3) * 16384 + 8192, hsrc + i * 4096, mb);
        }
    }

    // ---- ldmatrix lane addressing (same swizzle as packed tiles) ----
    const int bt = wid & 1, nh = wid >> 1;
    const int am = lane >> 3;
    const int arow = bt * 16 + (am & 1) * 8 + (lane & 7);   // A row (batch)
    const int qa   = am >> 1;
    const int sa   = arow & 7;
    const int brow = nh * 8 + (lane & 7);                   // B row (n)
    const int grp  = lane >> 3;
    const int sb   = brow & 7;
    const unsigned habase = sBase + 8192 + arow * 256;
    const unsigned wbbase = sBase + brow * 256;

    float d[2][4];
#pragma unroll
    for (int e = 0; e < 2; e++)
#pragma unroll
        for (int j = 0; j < 4; j++) d[e][j] = 0.f;

#pragma unroll 1
    for (int kt = 0; kt < 8; kt++) {
        mbar_wait0(mBase + kt * 8);

        const unsigned ha = habase + (kt & 3) * 16384;
        const unsigned wa = wbbase + (kt & 3) * 16384;
#pragma unroll
        for (int kp = 0; kp < 4; kp++) {
            unsigned b0, b1, b2, b3;
            asm volatile("ldmatrix.sync.aligned.m8n8.x4.shared.b16 {%0,%1,%2,%3}, [%4];"
                         : "=r"(b0), "=r"(b1), "=r"(b2), "=r"(b3)
                         : "r"(wa + (((4 * kp + grp) ^ sb) << 4)));
            unsigned a0, a1, a2, a3;
            asm volatile("ldmatrix.sync.aligned.m8n8.x4.shared.b16 {%0,%1,%2,%3}, [%4];"
                         : "=r"(a0), "=r"(a1), "=r"(a2), "=r"(a3)
                         : "r"(ha + (((4 * kp + qa) ^ sa) << 4)));
            asm volatile("mma.sync.aligned.m16n8k16.row.col.f32.bf16.bf16.f32 "
                         "{%0,%1,%2,%3}, {%4,%5,%6,%7}, {%8,%9}, {%0,%1,%2,%3};"
                         : "+f"(d[0][0]), "+f"(d[0][1]), "+f"(d[0][2]), "+f"(d[0][3])
                         : "r"(a0), "r"(a1), "r"(a2), "r"(a3), "r"(b0), "r"(b1));
            unsigned c0, c1, c2, c3;
            asm volatile("ldmatrix.sync.aligned.m8n8.x4.shared.b16 {%0,%1,%2,%3}, [%4];"
                         : "=r"(c0), "=r"(c1), "=r"(c2), "=r"(c3)
                         : "r"(ha + (((4 * kp + 2 + qa) ^ sa) << 4)));
            asm volatile("mma.sync.aligned.m16n8k16.row.col.f32.bf16.bf16.f32 "
                         "{%0,%1,%2,%3}, {%4,%5,%6,%7}, {%8,%9}, {%0,%1,%2,%3};"
                         : "+f"(d[1][0]), "+f"(d[1][1]), "+f"(d[1][2]), "+f"(d[1][3])
                         : "r"(c0), "r"(c1), "r"(c2), "r"(c3), "r"(b2), "r"(b3));
        }

        // refill ring: buffer (kt&3) is free once all warps finished this tile
        if (kt + 4 < 8) {
            __syncthreads();
            if (tx == 0) {
                int i = kt + 4;
                unsigned mb = mBase + i * 8;
                mbar_expect(mb, 16384);
                bulk_cp(sBase + (i & 3) * 16384,        wsrc + i * 4096, mb);
                bulk_cp(sBase + (i & 3) * 16384 + 8192, hsrc + i * 4096, mb);
            }
        }
    }

    float ds[4];
#pragma unroll
    for (int j = 0; j < 4; j++) ds[j] = d[0][j] + d[1][j];

    // fragment coords: ds[half*2+j] -> (b = pb + half*8, n = n0 + pn + j)
    const int g  = lane >> 2, tg = lane & 3;
    const int pn = nh * 8 + 2 * tg;
    const int pb = bt * 16 + g;

    // ---- pair combine: write partials, second arriver proceeds ----
    if (!thal) {
        float* pp = g_part + (pair * 2 + khalf) * 1024;
#pragma unroll
        for (int half = 0; half < 2; half++)
#pragma unroll
            for (int j = 0; j < 2; j++)
                pp[(pn + j) * 32 + pb + half * 8] = ds[half * 2 + j];
        __threadfence();
        __syncthreads();
        if (tx == 0) swin = atomicAdd(&g_flag[t * 64 + pair], 1);
        __syncthreads();
        if (swin == 0) return;               // first arriver: partner finishes
        __threadfence();                     // acquire
        const float* qq = g_part + (pair * 2 + (khalf ^ 1)) * 1024;
#pragma unroll
        for (int half = 0; half < 2; half++)
#pragma unroll
            for (int j = 0; j < 2; j++)
                ds[half * 2 + j] += __ldcg(&qq[(pn + j) * 32 + pb + half * 8]);
    }

    // ---- epilogue: drive + relu; write fp32 master, tiled bf16 operand, rnn ----
    {
        const int ncol = n0 + pn;
        float* __restrict__ hfn = g_hf[nxt];
        __nv_bfloat16* __restrict__ hbn = g_hb[nxt];
        const float* __restrict__ hfc = g_hf[cur];

        float iwv[2][4];
#pragma unroll
        for (int j = 0; j < 2; j++)
#pragma unroll
            for (int i = 0; i < 4; i++) iwv[j][i] = iw[i * H3 + ncol + j];

#pragma unroll
        for (int half = 0; half < 2; half++) {
            int b = pb + half * 8;
            float4 iv = ((const float4*)inp)[b * Tz + t];
            float v2[2];
#pragma unroll
            for (int j = 0; j < 2; j++) {
                int n = ncol + j;
                float drv = iv.x * iwv[j][0] + iv.y * iwv[j][1]
                          + iv.z * iwv[j][2] + iv.w * iwv[j][3];
                float hp = hfc[b * H3 + n];
                float v = fmaxf(0.9f * hp + 0.1f * (ds[half * 2 + j] + drv), 0.0f);
                v2[j] = v;
                hfn[b * H3 + n] = v;
                rnn[((size_t)(b * Tz + t)) * H3 + n] = v;
            }
            // tiled+swizzled bf16 write (pair n, n+1 shares one 4B slot)
            int n = ncol;
            int off = (n >> 7) * 4096 + b * 128 + ((((n >> 3) & 15) ^ (b & 7)) << 3) + (n & 7);
            __nv_bfloat162 pk;
            pk.x = __float2bfloat16(v2[0]);
            pk.y = __float2bfloat16(v2[1]);
            *(__nv_bfloat162*)&hbn[off] = pk;
        }
    }
}

// ---------------- heads: mean/std over masked (m1) region ----------------------
__global__ void head_kernel(const float* __restrict__ rnn,
                            const float* __restrict__ mean_w, const float* __restrict__ mean_b,
                            const float* __restrict__ std_w,  const float* __restrict__ std_b,
                            float* __restrict__ mean_out, float* __restrict__ std_out) {
    int warp = blockIdx.x * 8 + (threadIdx.x >> 5);   // = b*512 + t
    int lane = threadIdx.x & 31;
    const float* row = rnn + (size_t)warp * H3 + 2048;
    float sm = 0.0f, ss = 0.0f;
#pragma unroll 8
    for (int i = lane; i < Hh; i += 32) {
        float v = row[i];
        sm += v * mean_w[2048 + i];
        ss += v * std_w[2048 + i];
    }
#pragma unroll
    for (int off = 16; off; off >>= 1) {
        sm += __shfl_down_sync(0xFFFFFFFFu, sm, off);
        ss += __shfl_down_sync(0xFFFFFFFFu, ss, off);
    }
    if (lane == 0) {
        mean_out[warp] = sm + mean_b[0];
        float s = ss + std_b[0];
        std_out[warp] = fminf(fmaxf(s, -5.0f), 10.0f);
    }
}

// ---------------- hn_last copy --------------------------------------------------
__global__ void hn_kernel(const float* __restrict__ rnn, float* __restrict__ hn_out) {
    int idx = blockIdx.x * blockDim.x + threadIdx.x;
    if (idx >= Bz * H3) return;
    int b = idx / H3, n = idx - b * H3;
    hn_out[idx] = rnn[((size_t)(b * Tz + (Tz - 1))) * H3 + n];
}

// ---------------- launch ---------------------------------------------------------
extern "C" void kernel_launch(void* const* d_in, const int* in_sizes, int n_in,
                              void* d_out, int out_size) {
    const float* inp        = (const float*)d_in[0];   // [32,512,4]
    const float* hn         = (const float*)d_in[1];   // [1,32,3072]
    // d_in[2] = w_str2str (unused: its mask is all-zeros in the reference)
    const float* w_str2thal = (const float*)d_in[3];
    const float* w_m12m1    = (const float*)d_in[4];
    const float* w_m12str   = (const float*)d_in[5];
    const float* w_thal2m1  = (const float*)d_in[6];
    const float* fixedw     = (const float*)d_in[7];
    const float* inp_weight = (const float*)d_in[8];   // [4,3072]
    const float* mean_w     = (const float*)d_in[9];   // [1,3072]
    const float* mean_b     = (const float*)d_in[10];  // [1]
    const float* std_w      = (const float*)d_in[11];
    const float* std_b      = (const float*)d_in[12];
    // d_in[13] = sampling flag

    float* out      = (float*)d_out;
    float* mean_out = out;                         // 32*512
    float* std_out  = out + 16384;                 // 32*512
    float* hn_out   = out + 32768;                 // 32*3072
    float* rnn      = out + 131072;                // 32*512*3072

    cudaFuncSetAttribute(step_mma, cudaFuncAttributeMaxDynamicSharedMemorySize, 65536);

    prep_pack<<<(160 * 8 * 4096 + 255) / 256, 256>>>(w_str2thal, w_m12m1, w_m12str, w_thal2m1, fixedw);
    init_kernel<<<(Bz * H3 + 255) / 256, 256>>>(hn);

    for (int t = 0; t < Tz; t++)
        step_mma<<<160, 256, 65536>>>(t, inp, inp_weight, rnn);

    head_kernel<<<2048, 256>>>(rnn, mean_w, mean_b, std_w, std_b, mean_out, std_out);
    hn_kernel<<<(Bz * H3 + 255) / 256, 256>>>(rnn, hn_out);
}

// round 10
// speedup vs baseline: 1.2022x; 1.0345x over previous
#include <cuda_runtime.h>
#include <cuda_bf16.h>
#include <cstdint>

// ---------------------------------------------------------------------------
// RNN_MultiRegional_SAC — bf16 mma.sync + cp.async.bulk staging + PDL overlap.
// h = relu(0.9 h + 0.1 (h @ W^T + drive)), 512 steps, B=32, 3H=3072.
// Per-step kernels chained with Programmatic Dependent Launch: mbarrier init
// and all W staging run BEFORE cudaGridDependencySynchronize() (overlapped
// with the predecessor step); only h staging + compute + epilogue are exposed.
// W_rec: 5 nonzero 1024x1024 blocks bf16: [W00=-fixed, W02, W10, W21, W22]
// Grid 160 blocks/step, each 8 K128-tiles over a 32-n strip:
//   bid 0..63:   str  pair=bid>>1, khalf=bid&1 (W00 | W02)
//   bid 64..127: m1   pair=32+((bid-64)>>1)    (W21 | W22)
//   bid 128..159: thal (W10), no pairing
// Paired halves combine via gmem partials + per-(t,pair) atomic flag
// (second arriver finishes). fp32 master h; bf16 mma operands.
// Output (float32): [mean 32*512][std 32*512][hn_last 32*3072][rnn 32*512*3072]
// ---------------------------------------------------------------------------

#define Hh   1024
#define H3   3072
#define Bz   32
#define Tz   512
#define NEXC 717
#define HH   (Hh*Hh)

// Packed, per-block-contiguous, pre-swizzled W tiles: [bid 160][kt 8][4096 bf16]
__device__ __align__(256) __nv_bfloat16 g_Wp[160u * 8u * 4096u];   // 10 MB
__device__ __align__(256) float         g_hf[2][Bz * H3];          // fp32 master h [b][n]
// bf16 operand h, tiled+swizzled: 24 tiles of 4096 elems; tile tk holds k in
// [tk*128,(tk+1)*128): elem off = b*128 + ((((k>>3)&15)^(b&7))<<3) + (k&7)
__device__ __align__(256) __nv_bfloat16 g_hb[2][24 * 4096];
__device__ __align__(256) float         g_part[64 * 2 * 1024];     // [pair][khalf][n32*b32]
__device__ int g_flag[Tz * 64];                                     // per-(step,pair) arrivals

// ---------------- helpers ----------------
__device__ __forceinline__ unsigned smem_u32(const void* p) {
    return (unsigned)__cvta_generic_to_shared(p);
}
__device__ __forceinline__ void bulk_cp(unsigned dstS, const void* srcG, unsigned mbarS) {
    asm volatile("cp.async.bulk.shared::cta.global.mbarrier::complete_tx::bytes [%0], [%1], %2, [%3];"
                 :: "r"(dstS), "l"(srcG), "n"(8192), "r"(mbarS) : "memory");
}
__device__ __forceinline__ void mbar_init(unsigned mbarS) {
    asm volatile("mbarrier.init.shared.b64 [%0], 1;" :: "r"(mbarS) : "memory");
}
__device__ __forceinline__ void mbar_expect(unsigned mbarS, unsigned bytes) {
    asm volatile("mbarrier.arrive.expect_tx.shared.b64 _, [%0], %1;" :: "r"(mbarS), "r"(bytes) : "memory");
}
__device__ __forceinline__ void mbar_wait0(unsigned mbarS) {
    asm volatile(
        "{\n\t.reg .pred P;\n"
        "W_%=:\n\t"
        "mbarrier.try_wait.parity.acquire.cta.shared::cta.b64 P, [%0], 0, 0x989680;\n\t"
        "@P bra D_%=;\n\t"
        "bra W_%=;\n"
        "D_%=:\n\t}"
        :: "r"(mbarS) : "memory");
}

// ---------------- prep: pack W into per-block swizzled tiles + zero flags ------
__global__ void prep_pack(const float* __restrict__ w_str2thal,
                          const float* __restrict__ w_m12m1,
                          const float* __restrict__ w_m12str,
                          const float* __restrict__ w_thal2m1,
                          const float* __restrict__ fixedw) {
    int e = blockIdx.x * blockDim.x + threadIdx.x;
    if (e >= 160 * 8 * 4096) return;
    if (e < Tz * 64) g_flag[e] = 0;

    int bid = e >> 15;              // /32768
    int rem = e & 32767;
    int kt  = rem >> 12;
    int wi  = rem & 4095;
    int row = wi >> 7;              // n within 32-strip
    int chunkS = (wi >> 3) & 15;
    int chunk  = chunkS ^ (row & 7);
    int kl  = (chunk << 3) | (wi & 7);    // k within 128-tile

    int n0loc, region;
    if (bid < 64)       { int strip = bid >> 1;        n0loc = strip * 32; region = (bid & 1) ? 1 : 0; }
    else if (bid < 128) { int strip = (bid - 64) >> 1; n0loc = strip * 32; region = (bid & 1) ? 4 : 3; }
    else                { n0loc = (bid - 128) * 32;    region = 2; }

    int n = n0loc + row;
    int k = (kt << 7) + kl;
    int src = n * Hh + k;

    float val;
    if (region == 0)      val = -fixedw[src];
    else if (region == 1) { float v = fminf(fmaxf(w_m12str[src], 1e-10f), 1.0f);  val = (k < NEXC) ? v : 0.0f; }
    else if (region == 2) { float v = fminf(fmaxf(w_str2thal[src], 1e-10f), 1.0f); val = (k < (Hh/2)) ? v : -v; }
    else if (region == 3) val = fminf(fmaxf(w_thal2m1[src], 1e-10f), 1.0f);
    else                  { float v = fminf(fmaxf(w_m12m1[src], 1e-10f), 1.0f);   val = (k < NEXC) ? v : -v; }

    g_Wp[e] = __float2bfloat16(val);
}

// ---------------- init: hn ([b][n]) -> h masters --------------------------------
__global__ void init_kernel(const float* __restrict__ hn) {
    int idx = blockIdx.x * blockDim.x + threadIdx.x;
    if (idx >= Bz * H3) return;
    int b = idx / H3, n = idx - b * H3;
    float v = hn[idx];
    g_hf[0][idx] = v;
    int off = (n >> 7) * 4096 + b * 128 + ((((n >> 3) & 15) ^ (b & 7)) << 3) + (n & 7);
    g_hb[0][off] = __float2bfloat16(v);
}

// ---------------- per-step tensor-core kernel (PDL) ------------------------------
// 256 threads = 8 warps; warp = (bt = w&1: batch half, nh = w>>1: n-octet).
// smem: 8 W buffers (64KB, all prefetched pre-gridsync) + 4 H ring buffers (32KB).
__global__ void __launch_bounds__(256, 2) step_mma(int t,
                                                   const float* __restrict__ inp,
                                                   const float* __restrict__ iw,
                                                   float* __restrict__ rnn) {
    extern __shared__ __align__(256) unsigned char smem[];   // [0,64K): W, [64K,96K): H
    __shared__ __align__(8) unsigned long long mbar[16];      // 0..7 W, 8..15 H
    __shared__ int swin;

    const int tx   = threadIdx.x;
    const int bid  = blockIdx.x;
    const int wid  = tx >> 5;
    const int lane = tx & 31;
    const int cur  = t & 1, nxt = cur ^ 1;

    // ---- block decode ----
    int n0, pair, khalf, htile0;
    bool thal = false;
    if (bid < 64)       { int s = bid >> 1;        khalf = bid & 1; n0 = s * 32;        pair = s;      htile0 = khalf ? 16 : 0; }
    else if (bid < 128) { int s = (bid - 64) >> 1; khalf = bid & 1; n0 = 2048 + s * 32; pair = 32 + s; htile0 = khalf ? 16 : 8; }
    else                { int s = bid - 128;       khalf = 0;       n0 = 1024 + s * 32; pair = 0;      htile0 = 0; thal = true; }

    const __nv_bfloat16* __restrict__ wsrc = g_Wp + (size_t)bid * 32768;
    const __nv_bfloat16* __restrict__ hsrc = g_hb[cur] + htile0 * 4096;

    const unsigned sBase = smem_u32(smem);
    const unsigned hRegion = sBase + 65536;
    const unsigned mBase = smem_u32(mbar);

    // ---- pre-dependency prologue (overlaps predecessor step) ----
    if (tx == 0) {
#pragma unroll
        for (int i = 0; i < 16; i++) mbar_init(mBase + i * 8);
    }
    __syncthreads();
    if (tx == 0) {
#pragma unroll
        for (int i = 0; i < 8; i++) {
            unsigned mb = mBase + i * 8;
            mbar_expect(mb, 8192);
            bulk_cp(sBase + i * 8192, wsrc + i * 4096, mb);
        }
    }

    // ---- wait for predecessor step's h writes ----
#if __CUDA_ARCH__ >= 900
    cudaGridDependencySynchronize();
#endif

    // ---- h staging: first 4 tiles ----
    if (tx == 0) {
#pragma unroll
        for (int i = 0; i < 4; i++) {
            unsigned mb = mBase + (8 + i) * 8;
            mbar_expect(mb, 8192);
            bulk_cp(hRegion + i * 8192, hsrc + i * 4096, mb);
        }
    }

    // ---- ldmatrix lane addressing (same swizzle as packed tiles) ----
    const int bt = wid & 1, nh = wid >> 1;
    const int am = lane >> 3;
    const int arow = bt * 16 + (am & 1) * 8 + (lane & 7);   // A row (batch)
    const int qa   = am >> 1;
    const int sa   = arow & 7;
    const int brow = nh * 8 + (lane & 7);                   // B row (n)
    const int grp  = lane >> 3;
    const int sb   = brow & 7;
    const unsigned habase = hRegion + arow * 256;
    const unsigned wbbase = sBase + brow * 256;

    float d[2][4];
#pragma unroll
    for (int e = 0; e < 2; e++)
#pragma unroll
        for (int j = 0; j < 4; j++) d[e][j] = 0.f;

#pragma unroll 1
    for (int kt = 0; kt < 8; kt++) {
        mbar_wait0(mBase + kt * 8);              // W tile (prefetched early)
        mbar_wait0(mBase + (8 + kt) * 8);        // H tile

        const unsigned ha = habase + (kt & 3) * 8192;
        const unsigned wa = wbbase + kt * 8192;
#pragma unroll
        for (int kp = 0; kp < 4; kp++) {
            unsigned b0, b1, b2, b3;
            asm volatile("ldmatrix.sync.aligned.m8n8.x4.shared.b16 {%0,%1,%2,%3}, [%4];"
                         : "=r"(b0), "=r"(b1), "=r"(b2), "=r"(b3)
                         : "r"(wa + (((4 * kp + grp) ^ sb) << 4)));
            unsigned a0, a1, a2, a3;
            asm volatile("ldmatrix.sync.aligned.m8n8.x4.shared.b16 {%0,%1,%2,%3}, [%4];"
                         : "=r"(a0), "=r"(a1), "=r"(a2), "=r"(a3)
                         : "r"(ha + (((4 * kp + qa) ^ sa) << 4)));
            asm volatile("mma.sync.aligned.m16n8k16.row.col.f32.bf16.bf16.f32 "
                         "{%0,%1,%2,%3}, {%4,%5,%6,%7}, {%8,%9}, {%0,%1,%2,%3};"
                         : "+f"(d[0][0]), "+f"(d[0][1]), "+f"(d[0][2]), "+f"(d[0][3])
                         : "r"(a0), "r"(a1), "r"(a2), "r"(a3), "r"(b0), "r"(b1));
            unsigned c0, c1, c2, c3;
            asm volatile("ldmatrix.sync.aligned.m8n8.x4.shared.b16 {%0,%1,%2,%3}, [%4];"
                         : "=r"(c0), "=r"(c1), "=r"(c2), "=r"(c3)
                         : "r"(ha + (((4 * kp + 2 + qa) ^ sa) << 4)));
            asm volatile("mma.sync.aligned.m16n8k16.row.col.f32.bf16.bf16.f32 "
                         "{%0,%1,%2,%3}, {%4,%5,%6,%7}, {%8,%9}, {%0,%1,%2,%3};"
                         : "+f"(d[1][0]), "+f"(d[1][1]), "+f"(d[1][2]), "+f"(d[1][3])
                         : "r"(c0), "r"(c1), "r"(c2), "r"(c3), "r"(b2), "r"(b3));
        }

        // refill H ring: buffer (kt&3) free once all warps finished this tile
        if (kt + 4 < 8) {
            __syncthreads();
            if (tx == 0) {
                int i = kt + 4;
                unsigned mb = mBase + (8 + i) * 8;
                mbar_expect(mb, 8192);
                bulk_cp(hRegion + (i & 3) * 8192, hsrc + i * 4096, mb);
            }
        }
    }

    float ds[4];
#pragma unroll
    for (int j = 0; j < 4; j++) ds[j] = d[0][j] + d[1][j];

    // fragment coords: ds[half*2+j] -> (b = pb + half*8, n = n0 + pn + j)
    const int g  = lane >> 2, tg = lane & 3;
    const int pn = nh * 8 + 2 * tg;
    const int pb = bt * 16 + g;

    // ---- pair combine: write partials, second arriver proceeds ----
    if (!thal) {
        float* pp = g_part + (pair * 2 + khalf) * 1024;
#pragma unroll
        for (int half = 0; half < 2; half++)
#pragma unroll
            for (int j = 0; j < 2; j++)
                pp[(pn + j) * 32 + pb + half * 8] = ds[half * 2 + j];
        __threadfence();
        __syncthreads();
        if (tx == 0) swin = atomicAdd(&g_flag[t * 64 + pair], 1);
        __syncthreads();
        if (swin == 0) {
#if __CUDA_ARCH__ >= 900
            cudaTriggerProgrammaticLaunchCompletion();
#endif
            return;                          // first arriver: partner finishes
        }
        __threadfence();                     // acquire
        const float* qq = g_part + (pair * 2 + (khalf ^ 1)) * 1024;
#pragma unroll
        for (int half = 0; half < 2; half++)
#pragma unroll
            for (int j = 0; j < 2; j++)
                ds[half * 2 + j] += __ldcg(&qq[(pn + j) * 32 + pb + half * 8]);
    }

    // ---- epilogue: drive + relu; write fp32 master, tiled bf16 operand, rnn ----
    {
        const int ncol = n0 + pn;
        float* __restrict__ hfn = g_hf[nxt];
        __nv_bfloat16* __restrict__ hbn = g_hb[nxt];
        const float* __restrict__ hfc = g_hf[cur];

        float iwv[2][4];
#pragma unroll
        for (int j = 0; j < 2; j++)
#pragma unroll
            for (int i = 0; i < 4; i++) iwv[j][i] = iw[i * H3 + ncol + j];

#pragma unroll
        for (int half = 0; half < 2; half++) {
            int b = pb + half * 8;
            float4 iv = ((const float4*)inp)[b * Tz + t];
            float v2[2];
#pragma unroll
            for (int j = 0; j < 2; j++) {
                int n = ncol + j;
                float drv = iv.x * iwv[j][0] + iv.y * iwv[j][1]
                          + iv.z * iwv[j][2] + iv.w * iwv[j][3];
                float hp = hfc[b * H3 + n];
                float v = fmaxf(0.9f * hp + 0.1f * (ds[half * 2 + j] + drv), 0.0f);
                v2[j] = v;
                hfn[b * H3 + n] = v;
                rnn[((size_t)(b * Tz + t)) * H3 + n] = v;
            }
            int n = ncol;
            int off = (n >> 7) * 4096 + b * 128 + ((((n >> 3) & 15) ^ (b & 7)) << 3) + (n & 7);
            __nv_bfloat162 pk;
            pk.x = __float2bfloat16(v2[0]);
            pk.y = __float2bfloat16(v2[1]);
            *(__nv_bfloat162*)&hbn[off] = pk;
        }
    }
#if __CUDA_ARCH__ >= 900
    cudaTriggerProgrammaticLaunchCompletion();
#endif
}

// ---------------- heads: mean/std over masked (m1) region ----------------------
__global__ void head_kernel(const float* __restrict__ rnn,
                            const float* __restrict__ mean_w, const float* __restrict__ mean_b,
                            const float* __restrict__ std_w,  const float* __restrict__ std_b,
                            float* __restrict__ mean_out, float* __restrict__ std_out) {
    int warp = blockIdx.x * 8 + (threadIdx.x >> 5);   // = b*512 + t
    int lane = threadIdx.x & 31;
    const float* row = rnn + (size_t)warp * H3 + 2048;
    float sm = 0.0f, ss = 0.0f;
#pragma unroll 8
    for (int i = lane; i < Hh; i += 32) {
        float v = row[i];
        sm += v * mean_w[2048 + i];
        ss += v * std_w[2048 + i];
    }
#pragma unroll
    for (int off = 16; off; off >>= 1) {
        sm += __shfl_down_sync(0xFFFFFFFFu, sm, off);
        ss += __shfl_down_sync(0xFFFFFFFFu, ss, off);
    }
    if (lane == 0) {
        mean_out[warp] = sm + mean_b[0];
        float s = ss + std_b[0];
        std_out[warp] = fminf(fmaxf(s, -5.0f), 10.0f);
    }
}

// ---------------- hn_last copy --------------------------------------------------
__global__ void hn_kernel(const float* __restrict__ rnn, float* __restrict__ hn_out) {
    int idx = blockIdx.x * blockDim.x + threadIdx.x;
    if (idx >= Bz * H3) return;
    int b = idx / H3, n = idx - b * H3;
    hn_out[idx] = rnn[((size_t)(b * Tz + (Tz - 1))) * H3 + n];
}

// ---------------- launch ---------------------------------------------------------
extern "C" void kernel_launch(void* const* d_in, const int* in_sizes, int n_in,
                              void* d_out, int out_size) {
    const float* inp        = (const float*)d_in[0];   // [32,512,4]
    const float* hn         = (const float*)d_in[1];   // [1,32,3072]
    // d_in[2] = w_str2str (unused: its mask is all-zeros in the reference)
    const float* w_str2thal = (const float*)d_in[3];
    const float* w_m12m1    = (const float*)d_in[4];
    const float* w_m12str   = (const float*)d_in[5];
    const float* w_thal2m1  = (const float*)d_in[6];
    const float* fixedw     = (const float*)d_in[7];
    const float* inp_weight = (const float*)d_in[8];   // [4,3072]
    const float* mean_w     = (const float*)d_in[9];   // [1,3072]
    const float* mean_b     = (const float*)d_in[10];  // [1]
    const float* std_w      = (const float*)d_in[11];
    const float* std_b      = (const float*)d_in[12];
    // d_in[13] = sampling flag

    float* out      = (float*)d_out;
    float* mean_out = out;                         // 32*512
    float* std_out  = out + 16384;                 // 32*512
    float* hn_out   = out + 32768;                 // 32*3072
    float* rnn      = out + 131072;                // 32*512*3072

    cudaFuncSetAttribute(step_mma, cudaFuncAttributeMaxDynamicSharedMemorySize, 98304);

    prep_pack<<<(160 * 8 * 4096 + 255) / 256, 256>>>(w_str2thal, w_m12m1, w_m12str, w_thal2m1, fixedw);
    init_kernel<<<(Bz * H3 + 255) / 256, 256>>>(hn);

    cudaLaunchAttribute attrs[1];
    attrs[0].id = cudaLaunchAttributeProgrammaticStreamSerialization;
    attrs[0].val.programmaticStreamSerializationAllowed = 1;
    cudaLaunchConfig_t cfg = {};
    cfg.gridDim = dim3(160, 1, 1);
    cfg.blockDim = dim3(256, 1, 1);
    cfg.dynamicSmemBytes = 98304;
    cfg.stream = 0;
    cfg.attrs = attrs;
    cfg.numAttrs = 1;

    for (int t = 0; t < Tz; t++)
        cudaLaunchKernelEx(&cfg, step_mma, t, inp, inp_weight, rnn);

    head_kernel<<<2048, 256>>>(rnn, mean_w, mean_b, std_w, std_b, mean_out, std_out);
    hn_kernel<<<(Bz * H3 + 255) / 256, 256>>>(rnn, hn_out);
}